// round 2
// baseline (speedup 1.0000x reference)
#include <cuda_runtime.h>
#include <cstdint>

#define T_LEN 2048
#define B_SZ  256
#define IN_DIM 182
#define H_DIM  64
#define G3     192   // 3*H

// ~403 MB scratch for the input-projection output IG[B*T, 192]
__device__ float g_ig[(size_t)B_SZ * T_LEN * G3];

// ---------------------------------------------------------------------------
// Kernel A: IG = X(BT x 182) @ W_ih^T(182 x 192) + bias
// BM=64, BN=192 (full N), BK=16, 256 threads, per-thread tile 4x12.
// ---------------------------------------------------------------------------
__global__ __launch_bounds__(256) void ig_gemm(const float* __restrict__ X,
                                               const float* __restrict__ Wih,
                                               const float* __restrict__ bias)
{
    __shared__ float As[16][68];    // [k][m], padded (16B-aligned rows)
    __shared__ float Bs[16][196];   // [k][n], padded

    const int tid = threadIdx.x;
    const int mBase = blockIdx.x * 64;
    const int mg = tid >> 4;   // 0..15 : compute row group (4 rows)
    const int ng = tid & 15;   // 0..15 : compute col group (12 cols)
    const int lm = tid >> 4;   // loader group
    const int lk = tid & 15;   // loader k within tile

    float acc[4][12];
#pragma unroll
    for (int i = 0; i < 4; i++)
#pragma unroll
        for (int j = 0; j < 12; j++) acc[i][j] = 0.f;

    const int NT = (IN_DIM + 15) / 16;   // 12 k-tiles

    float aReg[4], bReg[12];
    // prefetch tile 0 into registers
#pragma unroll
    for (int i = 0; i < 4; i++) {
        int k = lk;
        aReg[i] = (k < IN_DIM) ? X[(size_t)(mBase + lm + i * 16) * IN_DIM + k] : 0.f;
    }
#pragma unroll
    for (int i = 0; i < 12; i++) {
        int k = lk;
        bReg[i] = (k < IN_DIM) ? Wih[(size_t)(lm + i * 16) * IN_DIM + k] : 0.f;
    }

    for (int t = 0; t < NT; t++) {
        // stage registers -> smem
#pragma unroll
        for (int i = 0; i < 4; i++)  As[lk][lm + i * 16] = aReg[i];
#pragma unroll
        for (int i = 0; i < 12; i++) Bs[lk][lm + i * 16] = bReg[i];
        __syncthreads();

        // prefetch next tile
        if (t + 1 < NT) {
            const int k0n = (t + 1) * 16;
#pragma unroll
            for (int i = 0; i < 4; i++) {
                int k = k0n + lk;
                aReg[i] = (k < IN_DIM) ? X[(size_t)(mBase + lm + i * 16) * IN_DIM + k] : 0.f;
            }
#pragma unroll
            for (int i = 0; i < 12; i++) {
                int k = k0n + lk;
                bReg[i] = (k < IN_DIM) ? Wih[(size_t)(lm + i * 16) * IN_DIM + k] : 0.f;
            }
        }

        // compute over this k-tile
#pragma unroll
        for (int k = 0; k < 16; k++) {
            float4 a4 = *(const float4*)&As[k][mg * 4];
            float b[12];
            *(float4*)&b[0] = *(const float4*)&Bs[k][ng * 12];
            *(float4*)&b[4] = *(const float4*)&Bs[k][ng * 12 + 4];
            *(float4*)&b[8] = *(const float4*)&Bs[k][ng * 12 + 8];
            float a[4] = {a4.x, a4.y, a4.z, a4.w};
#pragma unroll
            for (int i = 0; i < 4; i++)
#pragma unroll
                for (int j = 0; j < 12; j++)
                    acc[i][j] += a[i] * b[j];
        }
        __syncthreads();
    }

    // epilogue: add bias, store
    float bv[12];
#pragma unroll
    for (int j = 0; j < 12; j++) bv[j] = bias[ng * 12 + j];
#pragma unroll
    for (int i = 0; i < 4; i++) {
        size_t row = (size_t)(mBase + mg * 4 + i);
        float* o = &g_ig[row * G3 + ng * 12];
#pragma unroll
        for (int j = 0; j < 12; j++) o[j] = acc[i][j] + bv[j];
    }
}

// ---------------------------------------------------------------------------
// Kernel B: GRU scan. One CTA per batch element, 192 threads.
// Thread j owns gate-row j of W_hh (64 regs). h in smem.
//   r = sig(ig_r + hg_r); z = sig(ig_z + hg_z)
//   n = tanh(ig_n + r*(hg_n + bias_n));  h' = n + z*(h - n)
// Fused readout: out = sigmoid(hT @ w_out^T + out_bias)
// ---------------------------------------------------------------------------
__device__ __forceinline__ float fsigmoid(float x) {
    return __fdividef(1.f, 1.f + __expf(-x));
}
__device__ __forceinline__ float ftanh(float x) {
    // tanh(x) = 2*sigmoid(2x) - 1
    return __fdividef(2.f, 1.f + __expf(-2.f * x)) - 1.f;
}

__global__ __launch_bounds__(192) void gru_scan(const float* __restrict__ whh,    // [192,64]
                                                const float* __restrict__ bias_n, // [64]
                                                const float* __restrict__ wout,   // [2,64]
                                                const float* __restrict__ out_bias, // [2]
                                                float* __restrict__ out)          // [B,2]
{
    const int b = blockIdx.x;
    const int j = threadIdx.x;           // 0..191

    __shared__ float sh_h[64];
    __shared__ float sh_pre[192];        // j<128: ig+hg ; j>=128: ig_n
    __shared__ float sh_b[64];           // hg_n + bias_n

    // load W_hh row j into registers
    float w[64];
#pragma unroll
    for (int k = 0; k < 64; k++) w[k] = whh[j * 64 + k];

    const float bn = (j >= 128) ? bias_n[j - 128] : 0.f;

    if (j < 64) sh_h[j] = 0.f;

    const float* igp = g_ig + (size_t)b * T_LEN * G3 + j;
    float ig_next = igp[0];
    __syncthreads();

    for (int t = 0; t < T_LEN; t++) {
        const float igc = ig_next;
        if (t < T_LEN - 1) ig_next = igp[(size_t)(t + 1) * G3];

        // hg_j = dot(W_hh[j,:], h)
        float a0 = 0.f, a1 = 0.f, a2 = 0.f, a3 = 0.f;
#pragma unroll
        for (int k = 0; k < 64; k += 4) {
            float4 h4 = *(const float4*)&sh_h[k];
            a0 += w[k]     * h4.x;
            a1 += w[k + 1] * h4.y;
            a2 += w[k + 2] * h4.z;
            a3 += w[k + 3] * h4.w;
        }
        const float hg = (a0 + a1) + (a2 + a3);

        if (j < 128) {
            sh_pre[j] = igc + hg;
        } else {
            sh_pre[j] = igc;
            sh_b[j - 128] = hg + bn;
        }
        __syncthreads();

        if (j < 64) {
            const float r = fsigmoid(sh_pre[j]);
            const float z = fsigmoid(sh_pre[64 + j]);
            const float n = ftanh(sh_pre[128 + j] + r * sh_b[j]);
            const float h = sh_h[j];
            sh_h[j] = n + z * (h - n);
        }
        __syncthreads();
    }

    // readout: OUT=2
    if (j < 2) {
        float acc = 0.f;
#pragma unroll 8
        for (int k = 0; k < 64; k++) acc += wout[j * 64 + k] * sh_h[k];
        out[b * 2 + j] = fsigmoid(acc + out_bias[j]);
    }
}

// ---------------------------------------------------------------------------
extern "C" void kernel_launch(void* const* d_in, const int* in_sizes, int n_in,
                              void* d_out, int out_size)
{
    const float* x        = (const float*)d_in[0];   // (256,2048,182)
    const float* wih      = (const float*)d_in[1];   // (192,182)
    const float* whh      = (const float*)d_in[2];   // (192,64)
    const float* bias     = (const float*)d_in[3];   // (192,)
    const float* bias_n   = (const float*)d_in[4];   // (64,)
    const float* wout     = (const float*)d_in[5];   // (2,64)
    const float* out_bias = (const float*)d_in[6];   // (2,)
    float* out = (float*)d_out;                      // (256,2)

    const int BT = B_SZ * T_LEN;
    ig_gemm<<<BT / 64, 256>>>(x, wih, bias);
    gru_scan<<<B_SZ, 192>>>(whh, bias_n, wout, out_bias, out);
}